// round 2
// baseline (speedup 1.0000x reference)
#include <cuda_runtime.h>

#define BETA   0.95f
#define THRESH 1.0f

constexpr int NI = 80, NH = 256, NC = 2, T = 200, BATCH = 4096;
constexpr int NB   = 32;           // batch rows per block
constexpr int NBLK = BATCH / NB;   // 128 blocks
constexpr int NTHR = 256;          // 8 warps
constexpr int SROW = 36;           // padded row stride (floats): bank-conflict-free

// Transposed weights (i-major rows of NH) so per-i weight loads are coalesced.
__device__ float g_W1T[NI * NH];
__device__ float g_W2T[NH * NH];
__device__ float g_W3T[NH * NH];

__global__ void prep_transpose(const float* __restrict__ W1,
                               const float* __restrict__ W2,
                               const float* __restrict__ W3) {
    int idx = blockIdx.x * 256 + threadIdx.x;   // grid 256x256 covers 65536
    if (idx < NI * NH) {
        int i = idx >> 8, j = idx & 255;
        g_W1T[idx] = W1[j * NI + i];
    }
    if (idx < NH * NH) {
        int i = idx >> 8, j = idx & 255;
        g_W2T[idx] = W2[j * NH + i];
        g_W3T[idx] = W3[j * NH + i];
    }
}

// ---- packed f32x2 helpers (FFMA2 path: ptxas won't emit this from C++) ----
__device__ __forceinline__ unsigned long long pack2(float lo, float hi) {
    unsigned long long r;
    asm("mov.b64 %0, {%1, %2};" : "=l"(r)
        : "r"(__float_as_uint(lo)), "r"(__float_as_uint(hi)));
    return r;
}
__device__ __forceinline__ void fma2(unsigned long long& d,
                                     unsigned long long a, unsigned long long b) {
    asm("fma.rn.f32x2 %0, %1, %2, %0;" : "+l"(d) : "l"(a), "l"(b));
}
__device__ __forceinline__ void unpack2(unsigned long long v, float& lo, float& hi) {
    unsigned ulo, uhi;
    asm("mov.b64 {%0, %1}, %2;" : "=r"(ulo), "=r"(uhi) : "l"(v));
    lo = __uint_as_float(ulo); hi = __uint_as_float(uhi);
}

// snntorch Leaky, reset_mechanism='subtract':
//   reset from PREVIOUS mem, spike from UPDATED mem.
__device__ __forceinline__ float lif_update(float mo, float cur, float& spk) {
    float mn = BETA * mo + cur - ((mo > THRESH) ? THRESH : 0.0f);
    spk = (mn > THRESH) ? 1.0f : 0.0f;
    return mn;
}

// One layer. Activations transposed: sA[i*SROW + b]. Warp (jhalf, bg) covers
// j = jhalf*128 + jj*32 + lane (jj=0..3) and b = bg*8 .. bg*8+7 (4 f32x2 pairs).
// Per i: 2 broadcast LDS.128 (8 spikes), 4 coalesced scalar weight LDG,
// 4 (w,w) packs, 16 FFMA2. Accumulation order per output: bias + ascending i,
// one fma each -> bitwise identical to the scalar version.
template<int K>
__device__ __forceinline__ void layer_f32x2(
    const float* __restrict__ WT, const float* __restrict__ sA,
    const float* __restrict__ sbias, float* __restrict__ m,
    float* __restrict__ sout, int lane, int jbase /*jhalf*128+lane*/, int bgrp)
{
    unsigned long long acc[4][4];
#pragma unroll
    for (int jj = 0; jj < 4; jj++) {
        float bj = sbias[jbase + jj * 32];
        unsigned long long bp = pack2(bj, bj);
        acc[jj][0] = bp; acc[jj][1] = bp; acc[jj][2] = bp; acc[jj][3] = bp;
    }

    const float* wbase = WT + jbase;
#pragma unroll 4
    for (int i = 0; i < K; i++) {
        const ulonglong2* sp = (const ulonglong2*)(sA + i * SROW + bgrp);
        ulonglong2 s01 = sp[0];           // pairs (b0,b1),(b2,b3)
        ulonglong2 s23 = sp[1];           // pairs (b4,b5),(b6,b7)
        const float* wr = wbase + i * NH;
#pragma unroll
        for (int jj = 0; jj < 4; jj++) {
            float w = wr[jj * 32];
            unsigned long long wp = pack2(w, w);
            fma2(acc[jj][0], wp, s01.x);
            fma2(acc[jj][1], wp, s01.y);
            fma2(acc[jj][2], wp, s23.x);
            fma2(acc[jj][3], wp, s23.y);
        }
    }

    // Epilogue: LIF update + spike write. Each thread owns disjoint 8-b slices
    // of rows j (no races). Lane stride per jj is 1 j-row = SROW floats
    // (36 mod 32 = 4 banks) -> conflict-free vectorized shared access.
#pragma unroll
    for (int jj = 0; jj < 4; jj++) {
        float cur[8];
        unpack2(acc[jj][0], cur[0], cur[1]);
        unpack2(acc[jj][1], cur[2], cur[3]);
        unpack2(acc[jj][2], cur[4], cur[5]);
        unpack2(acc[jj][3], cur[6], cur[7]);
        float* mrow = m    + (jbase + jj * 32) * SROW + bgrp;
        float* srow = sout + (jbase + jj * 32) * SROW + bgrp;
        float4 m0 = *(float4*)(mrow);
        float4 m1v = *(float4*)(mrow + 4);
        float4 s0, s1v;
        m0.x  = lif_update(m0.x,  cur[0], s0.x);
        m0.y  = lif_update(m0.y,  cur[1], s0.y);
        m0.z  = lif_update(m0.z,  cur[2], s0.z);
        m0.w  = lif_update(m0.w,  cur[3], s0.w);
        m1v.x = lif_update(m1v.x, cur[4], s1v.x);
        m1v.y = lif_update(m1v.y, cur[5], s1v.y);
        m1v.z = lif_update(m1v.z, cur[6], s1v.z);
        m1v.w = lif_update(m1v.w, cur[7], s1v.w);
        *(float4*)(mrow)     = m0;
        *(float4*)(mrow + 4) = m1v;
        *(float4*)(srow)     = s0;
        *(float4*)(srow + 4) = s1v;
    }
}

__global__ void __launch_bounds__(NTHR, 1) snn_kernel(
    const float* __restrict__ x,
    const float* __restrict__ b1, const float* __restrict__ b2,
    const float* __restrict__ b3, const float* __restrict__ W4,
    const float* __restrict__ b4, float* __restrict__ out)
{
    extern __shared__ float sm[];
    float* sx  = sm;                    // 80  * SROW   (x_t transposed [i][b])
    float* sA0 = sx  + NI * SROW;       // 256 * SROW   (spike ping)
    float* sA1 = sA0 + NH * SROW;       // 256 * SROW   (spike pong)
    float* m1  = sA1 + NH * SROW;       // 256 * SROW
    float* m2  = m1  + NH * SROW;
    float* m3  = m2  + NH * SROW;
    float* sb1 = m3  + NH * SROW;       // NH
    float* sb2 = sb1 + NH;
    float* sb3 = sb2 + NH;
    float* sW4 = sb3 + NH;              // NC*NH
    float* sb4 = sW4 + NC * NH;         // NC
    float* m4  = sb4 + NC;              // NB*NC

    const int tid  = threadIdx.x;
    const int lane = tid & 31;
    const int wid  = tid >> 5;
    const int b0   = blockIdx.x * NB;

    const int jbase = (wid & 1) * 128 + lane;  // + jj*32
    const int bgrp  = (wid >> 1) * 8;

    for (int k = tid; k < 3 * NH * SROW; k += NTHR) m1[k] = 0.f;  // m1,m2,m3
    if (tid < NH) { sb1[tid] = b1[tid]; sb2[tid] = b2[tid]; sb3[tid] = b3[tid]; }
    for (int k = tid; k < NC * NH; k += NTHR) sW4[k] = W4[k];
    if (tid < NC) sb4[tid] = b4[tid];
    if (tid < NB * NC) m4[tid] = 0.f;
    __syncthreads();

    for (int t = 0; t < T; ++t) {
        // Stage x[:, :, t] transposed into sx[i*SROW + b].
        for (int k = tid; k < NB * NI; k += NTHR) {
            int b = k & 31, i = k >> 5;
            sx[i * SROW + b] = x[((size_t)(b0 + b) * NI + i) * T + t];
        }
        __syncthreads();   // also orders last step's L4 reads before sA0 reuse

        layer_f32x2<NI>(g_W1T, sx,  sb1, m1, sA0, lane, jbase, bgrp);
        __syncthreads();
        layer_f32x2<NH>(g_W2T, sA0, sb2, m2, sA1, lane, jbase, bgrp);
        __syncthreads();
        layer_f32x2<NH>(g_W3T, sA1, sb3, m3, sA0, lane, jbase, bgrp);
        __syncthreads();

        // Layer 4: 2 classes, 64 threads: thread = (b, c). Scalar LDS,
        // lanes hit consecutive banks (broadcast across the c-pair).
        if (tid < NB * NC) {
            const int b = tid >> 1, c = tid & 1;
            const float* sr = sA0 + b;
            const float* wr = sW4 + c * NH;
            float a0 = sb4[c], a1 = 0.f, a2 = 0.f, a3 = 0.f;
#pragma unroll 8
            for (int i = 0; i < NH; i += 4) {
                a0 = fmaf(sr[(i + 0) * SROW], wr[i + 0], a0);
                a1 = fmaf(sr[(i + 1) * SROW], wr[i + 1], a1);
                a2 = fmaf(sr[(i + 2) * SROW], wr[i + 2], a2);
                a3 = fmaf(sr[(i + 3) * SROW], wr[i + 3], a3);
            }
            float cur = (a0 + a1) + (a2 + a3);
            float spk;
            m4[tid] = lif_update(m4[tid], cur, spk);
            out[(size_t)t * (BATCH * NC) + b0 * NC + tid] = spk;
        }
        // Next iteration's x-stage __syncthreads() orders L4 spike reads
        // before layer-1 overwrites sA0.
    }
}

extern "C" void kernel_launch(void* const* d_in, const int* in_sizes, int n_in,
                              void* d_out, int out_size) {
    const float* x  = (const float*)d_in[0];
    const float* W1 = (const float*)d_in[1];
    const float* b1 = (const float*)d_in[2];
    const float* W2 = (const float*)d_in[3];
    const float* b2 = (const float*)d_in[4];
    const float* W3 = (const float*)d_in[5];
    const float* b3 = (const float*)d_in[6];
    const float* W4 = (const float*)d_in[7];
    const float* b4 = (const float*)d_in[8];
    float* out = (float*)d_out;

    prep_transpose<<<256, 256>>>(W1, W2, W3);

    const int smem_floats = NI * SROW + 5 * NH * SROW + 3 * NH + NC * NH + NC + NB * NC;
    const int smem_bytes  = smem_floats * (int)sizeof(float);
    cudaFuncSetAttribute(snn_kernel,
                         cudaFuncAttributeMaxDynamicSharedMemorySize, smem_bytes);
    snn_kernel<<<NBLK, NTHR, smem_bytes>>>(x, b1, b2, b3, W4, b4, out);
}

// round 3
// speedup vs baseline: 1.0007x; 1.0007x over previous
#include <cuda_runtime.h>

#define BETA   0.95f
#define THRESH 1.0f

constexpr int NI = 80, NH = 256, NC = 2, T = 200, BATCH = 4096;
constexpr int NB   = 32;           // batch rows per block
constexpr int NBLK = BATCH / NB;   // 128 blocks
constexpr int NTHR = 256;          // 8 warps
constexpr int SROW = 36;           // padded row stride (floats): bank-conflict-free

// Transposed weights (i-major rows of NH) so per-i weight loads are coalesced.
__device__ float g_W1T[NI * NH];
__device__ float g_W2T[NH * NH];
__device__ float g_W3T[NH * NH];

__global__ void prep_transpose(const float* __restrict__ W1,
                               const float* __restrict__ W2,
                               const float* __restrict__ W3) {
    int idx = blockIdx.x * 256 + threadIdx.x;   // grid 256x256 covers 65536
    if (idx < NI * NH) {
        int i = idx >> 8, j = idx & 255;
        g_W1T[idx] = W1[j * NI + i];
    }
    if (idx < NH * NH) {
        int i = idx >> 8, j = idx & 255;
        g_W2T[idx] = W2[j * NH + i];
        g_W3T[idx] = W3[j * NH + i];
    }
}

// ---- packed f32x2 helpers (FFMA2 path: ptxas won't emit this from C++) ----
__device__ __forceinline__ unsigned long long pack2(float lo, float hi) {
    unsigned long long r;
    asm("mov.b64 %0, {%1, %2};" : "=l"(r)
        : "r"(__float_as_uint(lo)), "r"(__float_as_uint(hi)));
    return r;
}
__device__ __forceinline__ void fma2(unsigned long long& d,
                                     unsigned long long a, unsigned long long b) {
    asm("fma.rn.f32x2 %0, %1, %2, %0;" : "+l"(d) : "l"(a), "l"(b));
}
__device__ __forceinline__ void unpack2(unsigned long long v, float& lo, float& hi) {
    unsigned ulo, uhi;
    asm("mov.b64 {%0, %1}, %2;" : "=r"(ulo), "=r"(uhi) : "l"(v));
    lo = __uint_as_float(ulo); hi = __uint_as_float(uhi);
}

// snntorch Leaky, reset_mechanism='subtract':
//   reset from PREVIOUS mem, spike from UPDATED mem.
__device__ __forceinline__ float lif_update(float mo, float cur, float& spk) {
    float mn = BETA * mo + cur - ((mo > THRESH) ? THRESH : 0.0f);
    spk = (mn > THRESH) ? 1.0f : 0.0f;
    return mn;
}

// One layer. Activations transposed: sA[i*SROW + b]. Warp (jhalf, bg) covers
// j = jhalf*128 + jj*32 + lane (jj=0..3) and b = bg*8 .. bg*8+7 (4 f32x2 pairs).
// Per i: 2 broadcast LDS.128 (8 spikes), 4 coalesced scalar weight LDG,
// 4 (w,w) packs, 16 FFMA2. Accumulation order per output: bias + ascending i,
// one fma each -> bitwise identical to the scalar version.
template<int K>
__device__ __forceinline__ void layer_f32x2(
    const float* __restrict__ WT, const float* __restrict__ sA,
    const float* __restrict__ sbias, float* __restrict__ m,
    float* __restrict__ sout, int lane, int jbase /*jhalf*128+lane*/, int bgrp)
{
    unsigned long long acc[4][4];
#pragma unroll
    for (int jj = 0; jj < 4; jj++) {
        float bj = sbias[jbase + jj * 32];
        unsigned long long bp = pack2(bj, bj);
        acc[jj][0] = bp; acc[jj][1] = bp; acc[jj][2] = bp; acc[jj][3] = bp;
    }

    const float* wbase = WT + jbase;
#pragma unroll 4
    for (int i = 0; i < K; i++) {
        const ulonglong2* sp = (const ulonglong2*)(sA + i * SROW + bgrp);
        ulonglong2 s01 = sp[0];           // pairs (b0,b1),(b2,b3)
        ulonglong2 s23 = sp[1];           // pairs (b4,b5),(b6,b7)
        const float* wr = wbase + i * NH;
#pragma unroll
        for (int jj = 0; jj < 4; jj++) {
            float w = wr[jj * 32];
            unsigned long long wp = pack2(w, w);
            fma2(acc[jj][0], wp, s01.x);
            fma2(acc[jj][1], wp, s01.y);
            fma2(acc[jj][2], wp, s23.x);
            fma2(acc[jj][3], wp, s23.y);
        }
    }

    // Epilogue: LIF update + spike write. Each thread owns disjoint 8-b slices
    // of rows j (no races). Lane stride per jj is 1 j-row = SROW floats
    // (36 mod 32 = 4 banks) -> conflict-free vectorized shared access.
#pragma unroll
    for (int jj = 0; jj < 4; jj++) {
        float cur[8];
        unpack2(acc[jj][0], cur[0], cur[1]);
        unpack2(acc[jj][1], cur[2], cur[3]);
        unpack2(acc[jj][2], cur[4], cur[5]);
        unpack2(acc[jj][3], cur[6], cur[7]);
        float* mrow = m    + (jbase + jj * 32) * SROW + bgrp;
        float* srow = sout + (jbase + jj * 32) * SROW + bgrp;
        float4 m0 = *(float4*)(mrow);
        float4 m1v = *(float4*)(mrow + 4);
        float4 s0, s1v;
        m0.x  = lif_update(m0.x,  cur[0], s0.x);
        m0.y  = lif_update(m0.y,  cur[1], s0.y);
        m0.z  = lif_update(m0.z,  cur[2], s0.z);
        m0.w  = lif_update(m0.w,  cur[3], s0.w);
        m1v.x = lif_update(m1v.x, cur[4], s1v.x);
        m1v.y = lif_update(m1v.y, cur[5], s1v.y);
        m1v.z = lif_update(m1v.z, cur[6], s1v.z);
        m1v.w = lif_update(m1v.w, cur[7], s1v.w);
        *(float4*)(mrow)     = m0;
        *(float4*)(mrow + 4) = m1v;
        *(float4*)(srow)     = s0;
        *(float4*)(srow + 4) = s1v;
    }
}

__global__ void __launch_bounds__(NTHR, 1) snn_kernel(
    const float* __restrict__ x,
    const float* __restrict__ b1, const float* __restrict__ b2,
    const float* __restrict__ b3, const float* __restrict__ W4,
    const float* __restrict__ b4, float* __restrict__ out)
{
    extern __shared__ float sm[];
    float* sx  = sm;                    // 80  * SROW   (x_t transposed [i][b])
    float* sA0 = sx  + NI * SROW;       // 256 * SROW   (spike ping)
    float* sA1 = sA0 + NH * SROW;       // 256 * SROW   (spike pong)
    float* m1  = sA1 + NH * SROW;       // 256 * SROW
    float* m2  = m1  + NH * SROW;
    float* m3  = m2  + NH * SROW;
    float* sb1 = m3  + NH * SROW;       // NH
    float* sb2 = sb1 + NH;
    float* sb3 = sb2 + NH;
    float* sW4 = sb3 + NH;              // NC*NH
    float* sb4 = sW4 + NC * NH;         // NC
    float* m4  = sb4 + NC;              // NB*NC

    const int tid  = threadIdx.x;
    const int lane = tid & 31;
    const int wid  = tid >> 5;
    const int b0   = blockIdx.x * NB;

    const int jbase = (wid & 1) * 128 + lane;  // + jj*32
    const int bgrp  = (wid >> 1) * 8;

    for (int k = tid; k < 3 * NH * SROW; k += NTHR) m1[k] = 0.f;  // m1,m2,m3
    if (tid < NH) { sb1[tid] = b1[tid]; sb2[tid] = b2[tid]; sb3[tid] = b3[tid]; }
    for (int k = tid; k < NC * NH; k += NTHR) sW4[k] = W4[k];
    if (tid < NC) sb4[tid] = b4[tid];
    if (tid < NB * NC) m4[tid] = 0.f;
    __syncthreads();

    for (int t = 0; t < T; ++t) {
        // Stage x[:, :, t] transposed into sx[i*SROW + b].
        for (int k = tid; k < NB * NI; k += NTHR) {
            int b = k & 31, i = k >> 5;
            sx[i * SROW + b] = x[((size_t)(b0 + b) * NI + i) * T + t];
        }
        __syncthreads();   // also orders last step's L4 reads before sA0 reuse

        layer_f32x2<NI>(g_W1T, sx,  sb1, m1, sA0, lane, jbase, bgrp);
        __syncthreads();
        layer_f32x2<NH>(g_W2T, sA0, sb2, m2, sA1, lane, jbase, bgrp);
        __syncthreads();
        layer_f32x2<NH>(g_W3T, sA1, sb3, m3, sA0, lane, jbase, bgrp);
        __syncthreads();

        // Layer 4: 2 classes, 64 threads: thread = (b, c). Scalar LDS,
        // lanes hit consecutive banks (broadcast across the c-pair).
        if (tid < NB * NC) {
            const int b = tid >> 1, c = tid & 1;
            const float* sr = sA0 + b;
            const float* wr = sW4 + c * NH;
            float a0 = sb4[c], a1 = 0.f, a2 = 0.f, a3 = 0.f;
#pragma unroll 8
            for (int i = 0; i < NH; i += 4) {
                a0 = fmaf(sr[(i + 0) * SROW], wr[i + 0], a0);
                a1 = fmaf(sr[(i + 1) * SROW], wr[i + 1], a1);
                a2 = fmaf(sr[(i + 2) * SROW], wr[i + 2], a2);
                a3 = fmaf(sr[(i + 3) * SROW], wr[i + 3], a3);
            }
            float cur = (a0 + a1) + (a2 + a3);
            float spk;
            m4[tid] = lif_update(m4[tid], cur, spk);
            out[(size_t)t * (BATCH * NC) + b0 * NC + tid] = spk;
        }
        // Next iteration's x-stage __syncthreads() orders L4 spike reads
        // before layer-1 overwrites sA0.
    }
}

extern "C" void kernel_launch(void* const* d_in, const int* in_sizes, int n_in,
                              void* d_out, int out_size) {
    const float* x  = (const float*)d_in[0];
    const float* W1 = (const float*)d_in[1];
    const float* b1 = (const float*)d_in[2];
    const float* W2 = (const float*)d_in[3];
    const float* b2 = (const float*)d_in[4];
    const float* W3 = (const float*)d_in[5];
    const float* b3 = (const float*)d_in[6];
    const float* W4 = (const float*)d_in[7];
    const float* b4 = (const float*)d_in[8];
    float* out = (float*)d_out;

    prep_transpose<<<256, 256>>>(W1, W2, W3);

    const int smem_floats = NI * SROW + 5 * NH * SROW + 3 * NH + NC * NH + NC + NB * NC;
    const int smem_bytes  = smem_floats * (int)sizeof(float);
    cudaFuncSetAttribute(snn_kernel,
                         cudaFuncAttributeMaxDynamicSharedMemorySize, smem_bytes);
    snn_kernel<<<NBLK, NTHR, smem_bytes>>>(x, b1, b2, b3, W4, b4, out);
}

// round 5
// speedup vs baseline: 5.0382x; 5.0346x over previous
#include <cuda_runtime.h>
#include <cuda_fp16.h>
#include <cstdint>

#define BETA   0.95f
#define THRESH 1.0f

constexpr int NI = 80, NH = 256, NC = 2, T = 200, BATCH = 4096;
constexpr int NB = 32, NBLK = BATCH / NB, NTHR = 256;

// A-fragment stream: per warp, frags in consumption order.
// L1: 30 frags  (kc 0..4) x (prod 0..2) x (mt 0..1)
// L2: 64 frags  (kc 0..15) x (split 0..1) x (mt 0..1)
// L3: 64 frags
constexpr int FRAGS_L1 = 30, FRAGS_L23 = 64;
constexpr int FPW = FRAGS_L1 + 2 * FRAGS_L23;      // 158
constexpr int L2BASE = 30, L3BASE = 94;
__device__ __align__(16) __half g_wfrag[8 * FPW * 256];   // 647168 B, L2-resident

// SMEM strides in halfs (conflict-free for the B-frag LDS.32 pattern)
constexpr int SKX = 88;    // x tiles [32 b][80 i]
constexpr int SKS = 264;   // spike tiles [32 b][256 i]

// ---- prep: pack split weights into m16n8k16 A-fragment lane order ----
__global__ void prep(const float* __restrict__ W1, const float* __restrict__ W2,
                     const float* __restrict__ W3) {
    int idx = blockIdx.x * 256 + threadIdx.x;      // over 8*158*256 halfs
    if (idx >= 8 * FPW * 256) return;
    int h = idx & 7;
    int l = (idx >> 3) & 31;
    int f = (idx >> 8) % FPW;
    int w = (idx >> 8) / FPW;
    const float* W; int K, kc, mt, split;
    if (f < L2BASE)      { int s = f >> 1; mt = f & 1; kc = s / 3; int p = s % 3;
                           split = (p == 2); W = W1; K = NI; }
    else if (f < L3BASE) { int g = f - L2BASE; kc = g >> 2; split = (g >> 1) & 1;
                           mt = g & 1; W = W2; K = NH; }
    else                 { int g = f - L3BASE; kc = g >> 2; split = (g >> 1) & 1;
                           mt = g & 1; W = W3; K = NH; }
    // m16n8k16 A-frag (row-major): regs a0..a3 as f16x2
    int r = (l >> 2) + ((h >> 1) & 1) * 8;
    int k = (l & 3) * 2 + (h & 1) + ((h >> 2) & 1) * 8;
    int j = w * 32 + mt * 16 + r;
    int i = kc * 16 + k;
    float v = W[j * K + i];                        // K=80 is exactly 5*16: no pad
    __half hv = __float2half_rn(v);
    if (split) hv = __float2half_rn(v - __half2float(hv));
    g_wfrag[idx] = hv;
}

__device__ __forceinline__ void mma16816(float* d, uint4 a, uint32_t b0, uint32_t b1) {
    asm volatile(
        "mma.sync.aligned.m16n8k16.row.col.f32.f16.f16.f32 "
        "{%0,%1,%2,%3}, {%4,%5,%6,%7}, {%8,%9}, {%0,%1,%2,%3};"
        : "+f"(d[0]), "+f"(d[1]), "+f"(d[2]), "+f"(d[3])
        : "r"(a.x), "r"(a.y), "r"(a.z), "r"(a.w), "r"(b0), "r"(b1));
}

// L2/L3 GEMM: D[32j x 32b] += Wsplit[32j x 256i] * spikes[256i x 32b]
__device__ __forceinline__ void gemm256(const __half* __restrict__ sB,
                                        const uint4* __restrict__ ab, int base,
                                        float acc[2][4][4], int l) {
#pragma unroll 4
    for (int kc = 0; kc < 16; kc++) {
        uint32_t bf[4][2];
#pragma unroll
        for (int nt = 0; nt < 4; nt++) {
            const uint32_t* p = (const uint32_t*)
                (sB + (nt * 8 + (l >> 2)) * SKS + kc * 16 + (l & 3) * 2);
            bf[nt][0] = p[0];
            bf[nt][1] = p[4];          // k+8
        }
#pragma unroll
        for (int sp = 0; sp < 2; sp++)
#pragma unroll
            for (int mt = 0; mt < 2; mt++) {
                uint4 a = ab[(base + kc * 4 + sp * 2 + mt) * 32 + l];
#pragma unroll
                for (int nt = 0; nt < 4; nt++)
                    mma16816(acc[mt][nt], a, bf[nt][0], bf[nt][1]);
            }
    }
}

// L1 GEMM: 3 split products (hh, hl, lh) over K=80
__device__ __forceinline__ void gemm80(const __half* __restrict__ sXhi,
                                       const __half* __restrict__ sXlo,
                                       const uint4* __restrict__ ab,
                                       float acc[2][4][4], int l) {
#pragma unroll
    for (int kc = 0; kc < 5; kc++) {
        uint32_t bh[4][2], bl[4][2];
#pragma unroll
        for (int nt = 0; nt < 4; nt++) {
            int off = (nt * 8 + (l >> 2)) * SKX + kc * 16 + (l & 3) * 2;
            const uint32_t* ph = (const uint32_t*)(sXhi + off);
            const uint32_t* pl = (const uint32_t*)(sXlo + off);
            bh[nt][0] = ph[0]; bh[nt][1] = ph[4];
            bl[nt][0] = pl[0]; bl[nt][1] = pl[4];
        }
#pragma unroll
        for (int p = 0; p < 3; p++) {
#pragma unroll
            for (int mt = 0; mt < 2; mt++) {
                uint4 a = ab[((kc * 3 + p) * 2 + mt) * 32 + l];
#pragma unroll
                for (int nt = 0; nt < 4; nt++) {
                    uint32_t b0 = (p == 1) ? bl[nt][0] : bh[nt][0];
                    uint32_t b1 = (p == 1) ? bl[nt][1] : bh[nt][1];
                    mma16816(acc[mt][nt], a, b0, b1);
                }
            }
        }
    }
}

__global__ void __launch_bounds__(NTHR, 1) snn_kernel(
    const float* __restrict__ x,
    const float* __restrict__ B1, const float* __restrict__ B2,
    const float* __restrict__ B3, const float* __restrict__ W4,
    const float* __restrict__ b4, float* __restrict__ out)
{
    extern __shared__ __align__(16) char smem[];
    __half* sXhi = (__half*)smem;                  // 32*88
    __half* sXlo = sXhi + 32 * SKX;
    __half* sS1  = sXlo + 32 * SKX;                // 32*264
    __half* sS2  = sS1 + 32 * SKS;
    float*  s3f  = (float*)(sS2 + 32 * SKS);       // [256 j][33] floats
    float*  w4s  = s3f + 256 * 33;                 // 512 floats

    const int tid = threadIdx.x, l = tid & 31, w = tid >> 5;
    const int b0 = blockIdx.x * NB;
    const int jw = w * 32;
    const uint4* ab = ((const uint4*)g_wfrag) + (size_t)w * FPW * 32;

    // per-thread bias values for the 4 j rows it owns per m-tile
    float bias1[2][2], bias2[2][2], bias3[2][2];
#pragma unroll
    for (int mt = 0; mt < 2; mt++)
#pragma unroll
        for (int rh = 0; rh < 2; rh++) {
            int j = jw + mt * 16 + (l >> 2) + rh * 8;
            bias1[mt][rh] = B1[j]; bias2[mt][rh] = B2[j]; bias3[mt][rh] = B3[j];
        }

    float m1[2][4][4], m2[2][4][4], m3[2][4][4];
#pragma unroll
    for (int mt = 0; mt < 2; mt++)
#pragma unroll
        for (int nt = 0; nt < 4; nt++)
#pragma unroll
            for (int d = 0; d < 4; d++) { m1[mt][nt][d] = 0.f; m2[mt][nt][d] = 0.f; m3[mt][nt][d] = 0.f; }

    float m4v = 0.f, b4v = 0.f;
    if (tid < NB * NC) b4v = b4[tid & 1];
    for (int k = tid; k < NC * NH; k += NTHR) w4s[k] = W4[k];
    __syncthreads();

    for (int t = 0; t < T; t++) {
        // stage x[:, :, t] hi/lo split
        for (int k = tid; k < NI * NB; k += NTHR) {
            int i = k >> 5, b = k & 31;
            float v = x[((size_t)(b0 + b) * NI + i) * T + t];
            __half hh = __float2half_rn(v);
            __half hl = __float2half_rn(v - __half2float(hh));
            sXhi[b * SKX + i] = hh;
            sXlo[b * SKX + i] = hl;
        }
        __syncthreads();

        float acc[2][4][4];

        // ---- layer 1 ----
#pragma unroll
        for (int mt = 0; mt < 2; mt++)
#pragma unroll
            for (int nt = 0; nt < 4; nt++)
#pragma unroll
                for (int d = 0; d < 4; d++) acc[mt][nt][d] = 0.f;
        gemm80(sXhi, sXlo, ab, acc, l);
#pragma unroll
        for (int mt = 0; mt < 2; mt++)
#pragma unroll
            for (int nt = 0; nt < 4; nt++)
#pragma unroll
                for (int d = 0; d < 4; d++) {
                    int rh = d >> 1, c = d & 1;
                    float cur = acc[mt][nt][d] + bias1[mt][rh];
                    float mo = m1[mt][nt][d];
                    float mn = BETA * mo + cur - ((mo > THRESH) ? THRESH : 0.0f);
                    m1[mt][nt][d] = mn;
                    int j = jw + mt * 16 + (l >> 2) + rh * 8;
                    int b = nt * 8 + (l & 3) * 2 + c;
                    sS1[b * SKS + j] = (mn > THRESH) ? __ushort_as_half((unsigned short)0x3C00)
                                                     : __ushort_as_half((unsigned short)0);
                }
        __syncthreads();

        // ---- layer 2 ----
#pragma unroll
        for (int mt = 0; mt < 2; mt++)
#pragma unroll
            for (int nt = 0; nt < 4; nt++)
#pragma unroll
                for (int d = 0; d < 4; d++) acc[mt][nt][d] = 0.f;
        gemm256(sS1, ab, L2BASE, acc, l);
#pragma unroll
        for (int mt = 0; mt < 2; mt++)
#pragma unroll
            for (int nt = 0; nt < 4; nt++)
#pragma unroll
                for (int d = 0; d < 4; d++) {
                    int rh = d >> 1, c = d & 1;
                    float cur = acc[mt][nt][d] + bias2[mt][rh];
                    float mo = m2[mt][nt][d];
                    float mn = BETA * mo + cur - ((mo > THRESH) ? THRESH : 0.0f);
                    m2[mt][nt][d] = mn;
                    int j = jw + mt * 16 + (l >> 2) + rh * 8;
                    int b = nt * 8 + (l & 3) * 2 + c;
                    sS2[b * SKS + j] = (mn > THRESH) ? __ushort_as_half((unsigned short)0x3C00)
                                                     : __ushort_as_half((unsigned short)0);
                }
        __syncthreads();

        // ---- layer 3 ----
#pragma unroll
        for (int mt = 0; mt < 2; mt++)
#pragma unroll
            for (int nt = 0; nt < 4; nt++)
#pragma unroll
                for (int d = 0; d < 4; d++) acc[mt][nt][d] = 0.f;
        gemm256(sS2, ab, L3BASE, acc, l);
#pragma unroll
        for (int mt = 0; mt < 2; mt++)
#pragma unroll
            for (int nt = 0; nt < 4; nt++)
#pragma unroll
                for (int d = 0; d < 4; d++) {
                    int rh = d >> 1, c = d & 1;
                    float cur = acc[mt][nt][d] + bias3[mt][rh];
                    float mo = m3[mt][nt][d];
                    float mn = BETA * mo + cur - ((mo > THRESH) ? THRESH : 0.0f);
                    m3[mt][nt][d] = mn;
                    int j = jw + mt * 16 + (l >> 2) + rh * 8;
                    int b = nt * 8 + (l & 3) * 2 + c;
                    s3f[j * 33 + b] = (mn > THRESH) ? 1.0f : 0.0f;
                }
        __syncthreads();

        // ---- layer 4: 2 classes on CUDA cores ----
        if (tid < NB * NC) {
            int b = tid >> 1, c = tid & 1;
            const float* sr = s3f + b;
            const float* wr = w4s + c * NH;
            float a0 = b4v, a1 = 0.f, a2 = 0.f, a3 = 0.f;
#pragma unroll 8
            for (int i = 0; i < NH; i += 4) {
                a0 = fmaf(sr[(i + 0) * 33], wr[i + 0], a0);
                a1 = fmaf(sr[(i + 1) * 33], wr[i + 1], a1);
                a2 = fmaf(sr[(i + 2) * 33], wr[i + 2], a2);
                a3 = fmaf(sr[(i + 3) * 33], wr[i + 3], a3);
            }
            float cur = (a0 + a1) + (a2 + a3);
            float mo = m4v;
            float mn = BETA * mo + cur - ((mo > THRESH) ? THRESH : 0.0f);
            m4v = mn;
            out[(size_t)t * (BATCH * NC) + b0 * NC + tid] = (mn > THRESH) ? 1.0f : 0.0f;
        }
        // s3f is not rewritten until layer-3 epilogue of t+1 (3 syncs away): safe.
    }
}

extern "C" void kernel_launch(void* const* d_in, const int* in_sizes, int n_in,
                              void* d_out, int out_size) {
    const float* x  = (const float*)d_in[0];
    const float* W1 = (const float*)d_in[1];
    const float* b1 = (const float*)d_in[2];
    const float* W2 = (const float*)d_in[3];
    const float* b2 = (const float*)d_in[4];
    const float* W3 = (const float*)d_in[5];
    const float* b3 = (const float*)d_in[6];
    const float* W4 = (const float*)d_in[7];
    const float* b4 = (const float*)d_in[8];
    float* out = (float*)d_out;

    prep<<<(8 * FPW * 256 + 255) / 256, 256>>>(W1, W2, W3);

    const int smem_bytes = (2 * 32 * SKX + 2 * 32 * SKS) * 2   // halfs
                         + (256 * 33 + NC * NH) * 4;           // floats
    cudaFuncSetAttribute(snn_kernel,
                         cudaFuncAttributeMaxDynamicSharedMemorySize, smem_bytes);
    snn_kernel<<<NBLK, NTHR, smem_bytes>>>(x, b1, b2, b3, W4, b4, out);
}

// round 6
// speedup vs baseline: 5.1911x; 1.0303x over previous
#include <cuda_runtime.h>
#include <cuda_fp16.h>
#include <cstdint>

#define BETA   0.95f
#define THRESH 1.0f

constexpr int NI = 80, NH = 256, NC = 2, T = 200, BATCH = 4096;
constexpr int NB = 32, NBLK = BATCH / NB, NTHR = 512;   // 16 warps, j-tile 16 each

// Per-warp A-fragment stream (consumption order):
// L1: 15 frags (kc 0..4 x prod{hh,lo,losplit}=0..2), L2: 32 (kc 0..15 x split), L3: 32
constexpr int FRAGS_L1 = 15, FRAGS_L23 = 32;
constexpr int FPW = FRAGS_L1 + 2 * FRAGS_L23;      // 79
constexpr int L2BASE = 15, L3BASE = 47;
__device__ __align__(16) __half g_wfrag[16 * FPW * 256];   // 647168 B, L2-resident

constexpr int SKX = 88;    // x tiles [32 b][80 i] halfs
constexpr int SKS = 264;   // spike tiles [32 b][256 i] halfs

// ---- prep: pack split weights into m16n8k16 A-fragment lane order ----
__global__ void prep(const float* __restrict__ W1, const float* __restrict__ W2,
                     const float* __restrict__ W3) {
    int idx = blockIdx.x * 256 + threadIdx.x;      // over 16*79*256 halfs
    if (idx >= 16 * FPW * 256) return;
    int h = idx & 7;
    int l = (idx >> 3) & 31;
    int f = (idx >> 8) % FPW;
    int w = (idx >> 8) / FPW;
    const float* W; int K, kc, split;
    if (f < L2BASE)      { kc = f / 3; int p = f % 3; split = (p == 2); W = W1; K = NI; }
    else if (f < L3BASE) { int g = f - L2BASE; kc = g >> 1; split = g & 1; W = W2; K = NH; }
    else                 { int g = f - L3BASE; kc = g >> 1; split = g & 1; W = W3; K = NH; }
    // m16n8k16 A-frag (row-major), regs a0..a3 as f16x2
    int r = (l >> 2) + ((h >> 1) & 1) * 8;
    int k = (l & 3) * 2 + (h & 1) + ((h >> 2) & 1) * 8;
    int j = w * 16 + r;
    int i = kc * 16 + k;
    float v = W[j * K + i];
    __half hv = __float2half_rn(v);
    if (split) hv = __float2half_rn(v - __half2float(hv));
    g_wfrag[idx] = hv;
}

__device__ __forceinline__ void mma16816(float* d, uint4 a, uint32_t b0, uint32_t b1) {
    asm volatile(
        "mma.sync.aligned.m16n8k16.row.col.f32.f16.f16.f32 "
        "{%0,%1,%2,%3}, {%4,%5,%6,%7}, {%8,%9}, {%0,%1,%2,%3};"
        : "+f"(d[0]), "+f"(d[1]), "+f"(d[2]), "+f"(d[3])
        : "r"(a.x), "r"(a.y), "r"(a.z), "r"(a.w), "r"(b0), "r"(b1));
}

// L2/L3: D[16j x 32b] += Wsplit[16j x 256i] * spikes[256i x 32b]
__device__ __forceinline__ void gemm256(const __half* __restrict__ sB,
                                        const uint4* __restrict__ ab, int base,
                                        float acc[4][4], int l) {
#pragma unroll 4
    for (int kc = 0; kc < 16; kc++) {
        uint32_t bf[4][2];
#pragma unroll
        for (int nt = 0; nt < 4; nt++) {
            const uint32_t* p = (const uint32_t*)
                (sB + (nt * 8 + (l >> 2)) * SKS + kc * 16 + (l & 3) * 2);
            bf[nt][0] = p[0];
            bf[nt][1] = p[4];          // k+8
        }
#pragma unroll
        for (int sp = 0; sp < 2; sp++) {
            uint4 a = ab[(base + kc * 2 + sp) * 32 + l];
#pragma unroll
            for (int nt = 0; nt < 4; nt++)
                mma16816(acc[nt], a, bf[nt][0], bf[nt][1]);
        }
    }
}

// L1: 3 split products (hi*hi, hi*lo, lo*hi) over K=80
__device__ __forceinline__ void gemm80(const __half* __restrict__ sXhi,
                                       const __half* __restrict__ sXlo,
                                       const uint4* __restrict__ ab,
                                       float acc[4][4], int l) {
#pragma unroll
    for (int kc = 0; kc < 5; kc++) {
        uint32_t bh[4][2], bl[4][2];
#pragma unroll
        for (int nt = 0; nt < 4; nt++) {
            int off = (nt * 8 + (l >> 2)) * SKX + kc * 16 + (l & 3) * 2;
            const uint32_t* ph = (const uint32_t*)(sXhi + off);
            const uint32_t* pl = (const uint32_t*)(sXlo + off);
            bh[nt][0] = ph[0]; bh[nt][1] = ph[4];
            bl[nt][0] = pl[0]; bl[nt][1] = pl[4];
        }
#pragma unroll
        for (int p = 0; p < 3; p++) {
            uint4 a = ab[(kc * 3 + p) * 32 + l];
#pragma unroll
            for (int nt = 0; nt < 4; nt++) {
                uint32_t b0 = (p == 1) ? bl[nt][0] : bh[nt][0];
                uint32_t b1 = (p == 1) ? bl[nt][1] : bh[nt][1];
                mma16816(acc[nt], a, b0, b1);
            }
        }
    }
}

__global__ void __launch_bounds__(NTHR, 1) snn_kernel(
    const float* __restrict__ x,
    const float* __restrict__ B1, const float* __restrict__ B2,
    const float* __restrict__ B3, const float* __restrict__ W4,
    const float* __restrict__ b4, float* __restrict__ out)
{
    extern __shared__ __align__(16) char smem[];
    __half* sXhi = (__half*)smem;                  // 32*88
    __half* sXlo = sXhi + 32 * SKX;
    __half* sS1  = sXlo + 32 * SKX;                // 32*264
    __half* sS2  = sS1 + 32 * SKS;
    float*  s3f  = (float*)(sS2 + 32 * SKS);       // [256 j][33] floats
    float*  w4s  = s3f + 256 * 33;                 // 512 floats

    const int tid = threadIdx.x, l = tid & 31, w = tid >> 5;
    const int b0 = blockIdx.x * NB;
    const int jw = w * 16;
    const uint4* ab = ((const uint4*)g_wfrag) + (size_t)w * FPW * 32;

    float bias1[2], bias2[2], bias3[2];
#pragma unroll
    for (int rh = 0; rh < 2; rh++) {
        int j = jw + (l >> 2) + rh * 8;
        bias1[rh] = B1[j]; bias2[rh] = B2[j]; bias3[rh] = B3[j];
    }

    float m1[4][4], m2[4][4], m3[4][4];
#pragma unroll
    for (int nt = 0; nt < 4; nt++)
#pragma unroll
        for (int d = 0; d < 4; d++) { m1[nt][d] = 0.f; m2[nt][d] = 0.f; m3[nt][d] = 0.f; }

    float m4v = 0.f, b4v = 0.f;
    if (tid < NB * NC) b4v = b4[tid & 1];
    for (int k = tid; k < NC * NH; k += NTHR) w4s[k] = W4[k];
    __syncthreads();

    for (int t = 0; t < T; t++) {
        // stage x[:, :, t] hi/lo split
        for (int k = tid; k < NI * NB; k += NTHR) {
            int i = k >> 5, b = k & 31;
            float v = x[((size_t)(b0 + b) * NI + i) * T + t];
            __half hh = __float2half_rn(v);
            __half hl = __float2half_rn(v - __half2float(hh));
            sXhi[b * SKX + i] = hh;
            sXlo[b * SKX + i] = hl;
        }
        __syncthreads();

        float acc[4][4];

        // ---- layer 1 ----
#pragma unroll
        for (int nt = 0; nt < 4; nt++)
#pragma unroll
            for (int d = 0; d < 4; d++) acc[nt][d] = 0.f;
        gemm80(sXhi, sXlo, ab, acc, l);
#pragma unroll
        for (int nt = 0; nt < 4; nt++)
#pragma unroll
            for (int d = 0; d < 4; d++) {
                int rh = d >> 1, c = d & 1;
                float cur = acc[nt][d] + bias1[rh];
                float mo = m1[nt][d];
                float mn = BETA * mo + cur - ((mo > THRESH) ? THRESH : 0.0f);
                m1[nt][d] = mn;
                int j = jw + (l >> 2) + rh * 8;
                int b = nt * 8 + (l & 3) * 2 + c;
                sS1[b * SKS + j] = (mn > THRESH) ? __ushort_as_half((unsigned short)0x3C00)
                                                 : __ushort_as_half((unsigned short)0);
            }
        __syncthreads();

        // ---- layer 2 ----
#pragma unroll
        for (int nt = 0; nt < 4; nt++)
#pragma unroll
            for (int d = 0; d < 4; d++) acc[nt][d] = 0.f;
        gemm256(sS1, ab, L2BASE, acc, l);
#pragma unroll
        for (int nt = 0; nt < 4; nt++)
#pragma unroll
            for (int d = 0; d < 4; d++) {
                int rh = d >> 1, c = d & 1;
                float cur = acc[nt][d] + bias2[rh];
                float mo = m2[nt][d];
                float mn = BETA * mo + cur - ((mo > THRESH) ? THRESH : 0.0f);
                m2[nt][d] = mn;
                int j = jw + (l >> 2) + rh * 8;
                int b = nt * 8 + (l & 3) * 2 + c;
                sS2[b * SKS + j] = (mn > THRESH) ? __ushort_as_half((unsigned short)0x3C00)
                                                 : __ushort_as_half((unsigned short)0);
            }
        __syncthreads();

        // ---- layer 3 ----
#pragma unroll
        for (int nt = 0; nt < 4; nt++)
#pragma unroll
            for (int d = 0; d < 4; d++) acc[nt][d] = 0.f;
        gemm256(sS2, ab, L3BASE, acc, l);
#pragma unroll
        for (int nt = 0; nt < 4; nt++)
#pragma unroll
            for (int d = 0; d < 4; d++) {
                int rh = d >> 1, c = d & 1;
                float cur = acc[nt][d] + bias3[rh];
                float mo = m3[nt][d];
                float mn = BETA * mo + cur - ((mo > THRESH) ? THRESH : 0.0f);
                m3[nt][d] = mn;
                int j = jw + (l >> 2) + rh * 8;
                int b = nt * 8 + (l & 3) * 2 + c;
                s3f[j * 33 + b] = (mn > THRESH) ? 1.0f : 0.0f;
            }
        __syncthreads();

        // ---- layer 4: 2 classes on CUDA cores ----
        if (tid < NB * NC) {
            int b = tid >> 1, c = tid & 1;
            const float* sr = s3f + b;
            const float* wr = w4s + c * NH;
            float a0 = b4v, a1 = 0.f, a2 = 0.f, a3 = 0.f;
#pragma unroll 8
            for (int i = 0; i < NH; i += 4) {
                a0 = fmaf(sr[(i + 0) * 33], wr[i + 0], a0);
                a1 = fmaf(sr[(i + 1) * 33], wr[i + 1], a1);
                a2 = fmaf(sr[(i + 2) * 33], wr[i + 2], a2);
                a3 = fmaf(sr[(i + 3) * 33], wr[i + 3], a3);
            }
            float cur = (a0 + a1) + (a2 + a3);
            float mo = m4v;
            float mn = BETA * mo + cur - ((mo > THRESH) ? THRESH : 0.0f);
            m4v = mn;
            out[(size_t)t * (BATCH * NC) + b0 * NC + tid] = (mn > THRESH) ? 1.0f : 0.0f;
        }
        // s3f not rewritten until layer-3 epilogue of t+1 (3 syncs away): safe.
    }
}

extern "C" void kernel_launch(void* const* d_in, const int* in_sizes, int n_in,
                              void* d_out, int out_size) {
    const float* x  = (const float*)d_in[0];
    const float* W1 = (const float*)d_in[1];
    const float* b1 = (const float*)d_in[2];
    const float* W2 = (const float*)d_in[3];
    const float* b2 = (const float*)d_in[4];
    const float* W3 = (const float*)d_in[5];
    const float* b3 = (const float*)d_in[6];
    const float* W4 = (const float*)d_in[7];
    const float* b4 = (const float*)d_in[8];
    float* out = (float*)d_out;

    prep<<<(16 * FPW * 256 + 255) / 256, 256>>>(W1, W2, W3);

    const int smem_bytes = (2 * 32 * SKX + 2 * 32 * SKS) * 2   // halfs
                         + (256 * 33 + NC * NH) * 4;           // floats
    cudaFuncSetAttribute(snn_kernel,
                         cudaFuncAttributeMaxDynamicSharedMemorySize, smem_bytes);
    snn_kernel<<<NBLK, NTHR, smem_bytes>>>(x, b1, b2, b3, W4, b4, out);
}